// round 12
// baseline (speedup 1.0000x reference)
#include <cuda_runtime.h>
#include <cuda_bf16.h>
#include <cstdint>

#define BATCH 32
#define SLEN  128
#define TLEN  64
#define VOC   32000
#define EMB   256
#define HID   512
#define G3    1536            // 3*HID
#define BT    (BATCH*TLEN)    // 2048 decoder rows
#define SB    (SLEN*BATCH)    // 4096 encoder rows
#define RNBLK 128             // persistent recurrence blocks (<=148 SMs)
#define NBLKS (VOC/64)        // 500 n-blocks in output projection

// ---------------- scratch (device globals; no allocation allowed) ----------
__device__ float g_gx  [SB*G3];               // [s][b][3H]
__device__ float g_gi  [BT*G3];               // [t][b][3H]
__device__ float g_p   [BATCH*G3];            // ctx @ Wp^T + bp
__device__ float g_h   [2][BATCH*HID];        // hidden ping-pong (enc then dec)
__device__ __nv_bfloat16 g_hb[BT*HID];        // bf16 decoder outputs, row = b*T+t
__device__ __nv_bfloat16 g_Wb[VOC*HID];       // bf16 copy of out_W
__device__ float2 g_part[(size_t)BT*NBLKS];   // per (row, nblk) {max, sumexp}
__device__ float g_tgt[BT];                   // target logit per row (with bias)
__device__ float g_rownll[BT];
__device__ unsigned g_barE, g_barD;

__device__ __forceinline__ float sigf(float x) { return 1.0f / (1.0f + __expf(-x)); }

__global__ void k_reset_bars() { g_barE = 0; g_barD = 0; }

__global__ void k_zero_h0() {
    int i = blockIdx.x * 256 + threadIdx.x;
    if (i < BATCH * HID) g_h[0][i] = 0.0f;
}

// ---------------- input GEMM:  out[m][n] = A_row(m) . W[n][:] + bias[n] -----
__global__ void k_big_gemm(const float* __restrict__ Asrc,
                           const int* __restrict__ ids, int ids_len,
                           int rows, int K,
                           const float* __restrict__ W,
                           const float* __restrict__ bias,
                           int outsel, int a_from_ctx) {
    __shared__ __align__(16) float As[16][72];   // [kk][m]
    __shared__ __align__(16) float Bs[16][72];   // [kk][n]
    __shared__ int sIds[64];

    float* out = (outsel == 0) ? g_gx : (outsel == 1) ? g_gi : g_p;
    const float* Abase = a_from_ctx ? g_h[0] : Asrc;

    int tid = threadIdx.x;                // 256 threads
    int m0 = blockIdx.y * 64, n0 = blockIdx.x * 64;
    int ty = tid / 16, tx = tid % 16;

    if (ids) {
        for (int i = tid; i < 64; i += 256) {
            int m = m0 + i;
            sIds[i] = (m < rows) ? ids[(m % BATCH) * ids_len + (m / BATCH)] : 0;
        }
        __syncthreads();
    }

    float acc[4][4];
#pragma unroll
    for (int i = 0; i < 4; i++)
#pragma unroll
        for (int j = 0; j < 4; j++) acc[i][j] = 0.0f;

    for (int k0 = 0; k0 < K; k0 += 16) {
        for (int i = tid; i < 1024; i += 256) {
            int r = i / 16, kk = i % 16;
            int m = m0 + r;
            float v = 0.0f;
            if (m < rows) {
                const float* ap = ids ? (Abase + (size_t)sIds[r] * K)
                                      : (Abase + (size_t)m * K);
                v = ap[k0 + kk];
            }
            As[kk][r] = v;
        }
        for (int i = tid; i < 1024; i += 256) {
            int n = i / 16, kk = i % 16;
            Bs[kk][n] = W[(size_t)(n0 + n) * K + k0 + kk];
        }
        __syncthreads();
#pragma unroll
        for (int kk = 0; kk < 16; kk++) {
            float4 a4 = *(const float4*)&As[kk][ty * 4];
            float4 b4 = *(const float4*)&Bs[kk][tx * 4];
            float a[4] = {a4.x, a4.y, a4.z, a4.w};
            float b[4] = {b4.x, b4.y, b4.z, b4.w};
#pragma unroll
            for (int i = 0; i < 4; i++)
#pragma unroll
                for (int j = 0; j < 4; j++) acc[i][j] += a[i] * b[j];
        }
        __syncthreads();
    }

#pragma unroll
    for (int i = 0; i < 4; i++) {
        int m = m0 + ty * 4 + i;
        if (m >= rows) continue;
#pragma unroll
        for (int j = 0; j < 4; j++) {
            int n = n0 + tx * 4 + j;
            out[(size_t)m * G3 + n] = acc[i][j] + bias[n];
        }
    }
}

// ---------------- persistent recurrence v2 ----------------------------------
// 128 blocks x 384 thr (12 warps). Block owns 4 h-cols (12 gate cols).
// Dot: warp = (col-group cw of 4 cols, k-chunk kc of 128); lane = (cl, o),
// computes 4 batch outputs (o, o+8, o+16, o+24). Partials reduced via smem.
// Grid barrier: single-thread release/acquire atomics.
template<int STEPS, bool DEC>
__global__ void __launch_bounds__(384, 1)
k_recur(const float* __restrict__ Wrec,   // [G3][HID] row-major
        const float* __restrict__ brec,   // [G3]
        const int* __restrict__ src_len)  // encoder only
{
    extern __shared__ float sm[];
    float* Wsm = sm;                       // 12*520
    float* hsm = Wsm + 12 * 520;           // 32*516
    float* red = hsm + 32 * 516;           // 4*384 partials
    float* ghm = red + 4 * 384;            // 384 reduced gates

    const int t = threadIdx.x;
    const int j0 = blockIdx.x * 4;

    // cache weight slice (12 gate rows x 512) in smem, padded to 520
    for (int i = t; i < 12 * 512; i += 384) {
        int gc = i >> 9, k = i & 511;
        Wsm[gc * 520 + k] = Wrec[(size_t)((gc >> 2) * 512 + j0 + (gc & 3)) * 512 + k];
    }

    // dot-role constants
    const int w  = t >> 5;                 // warp 0..11
    const int kc = w & 3;                  // k-chunk
    const int cw = w >> 2;                 // col-group 0..2
    const int lane = t & 31;
    const int cl = lane >> 3, o = lane & 7;
    const int gc_d = cw * 4 + cl;

    // reduce-role constants
    const int gc_r = t >> 5;               // 0..11
    const int b_r  = t & 31;
    const float biasr = brec[(gc_r >> 2) * 512 + j0 + (gc_r & 3)];

    // combine-role constants (t < 128)
    const int hc = t >> 5, bc = t & 31;    // valid when t<128
    const int jc = j0 + hc;
    float p0 = 0.f, p1 = 0.f, p2 = 0.f;
    int slen = 0;
    if (t < 128) {
        if (DEC) {
            p0 = g_p[bc * G3 + jc];
            p1 = g_p[bc * G3 + 512 + jc];
            p2 = g_p[bc * G3 + 1024 + jc];
        } else {
            slen = src_len[bc];
        }
    }
    __syncthreads();

    unsigned* bar = DEC ? &g_barD : &g_barE;
    const float* gbase = DEC ? g_gi : g_gx;

    for (int s = 0; s < STEPS; s++) {
        const float* hprev = g_h[s & 1];
        float* hnext = g_h[(s + 1) & 1];

        // prefetch this step's input-gate values (used in combine)
        float gx0 = 0.f, gx1 = 0.f, gx2 = 0.f;
        if (t < 128) {
            const float* gr = gbase + ((size_t)s * BATCH + bc) * G3;
            gx0 = gr[jc]; gx1 = gr[512 + jc]; gx2 = gr[1024 + jc];
        }

        // stage h[32][512] to smem
        for (int f = t; f < 4096; f += 384) {
            int b = f >> 7, kq = f & 127;
            float4 v = __ldcg((const float4*)(hprev + b * 512 + kq * 4));
            *(float4*)(hsm + b * 516 + kq * 4) = v;
        }
        __syncthreads();

        // dot partials: 4 batches per lane over a 128-k chunk
        {
            const float* wp = Wsm + gc_d * 520 + kc * 128;
            const float* h0 = hsm + (o     ) * 516 + kc * 128;
            const float* h1 = hsm + (o +  8) * 516 + kc * 128;
            const float* h2 = hsm + (o + 16) * 516 + kc * 128;
            const float* h3 = hsm + (o + 24) * 516 + kc * 128;
            float a0 = 0.f, a1 = 0.f, a2 = 0.f, a3 = 0.f;
#pragma unroll 8
            for (int k = 0; k < 128; k += 4) {
                float4 wv = *(const float4*)(wp + k);
                float4 v0 = *(const float4*)(h0 + k);
                float4 v1 = *(const float4*)(h1 + k);
                float4 v2 = *(const float4*)(h2 + k);
                float4 v3 = *(const float4*)(h3 + k);
                a0 += wv.x * v0.x + wv.y * v0.y + wv.z * v0.z + wv.w * v0.w;
                a1 += wv.x * v1.x + wv.y * v1.y + wv.z * v1.z + wv.w * v1.w;
                a2 += wv.x * v2.x + wv.y * v2.y + wv.z * v2.z + wv.w * v2.w;
                a3 += wv.x * v3.x + wv.y * v3.y + wv.z * v3.z + wv.w * v3.w;
            }
            float* rp = red + kc * 384 + gc_d * 32;
            rp[o] = a0; rp[o + 8] = a1; rp[o + 16] = a2; rp[o + 24] = a3;
        }
        __syncthreads();

        // reduce 4 k-chunks + bias
        ghm[gc_r * 32 + b_r] = red[gc_r * 32 + b_r] + red[384 + gc_r * 32 + b_r]
                             + red[768 + gc_r * 32 + b_r] + red[1152 + gc_r * 32 + b_r]
                             + biasr;
        __syncthreads();

        // combine gates + write new h
        if (t < 128) {
            float ghr = ghm[hc * 32 + bc];
            float ghz = ghm[(4 + hc) * 32 + bc];
            float ghn = ghm[(8 + hc) * 32 + bc];
            float hold = hsm[bc * 516 + jc];
            float hy;
            if (DEC) {
                float r  = sigf(gx0 + ghr + p0);
                float ig = sigf(gx1 + ghz + p1);
                float nn = tanhf(gx2 + r * ghn + p2);
                hy = nn + ig * (hold - nn);
                g_hb[((size_t)bc * TLEN + s) * HID + jc] = __float2bfloat16(hy);
            } else {
                float r  = sigf(gx0 + ghr);
                float z  = sigf(gx1 + ghz);
                float nn = tanhf(gx2 + r * ghn);
                float hn = (1.0f - z) * nn + z * hold;
                hy = (s < slen) ? hn : hold;
            }
            __stcg(hnext + bc * 512 + jc, hy);
        }

        // grid barrier (release/acquire, single thread)
        if (s + 1 < STEPS) {
            __syncthreads();
            if (t == 0) {
                asm volatile("red.release.gpu.global.add.u32 [%0], %1;"
                             :: "l"(bar), "r"(1u) : "memory");
                unsigned target = (unsigned)(s + 1) * RNBLK;
                unsigned v;
                do {
                    asm volatile("ld.acquire.gpu.global.u32 %0, [%1];"
                                 : "=r"(v) : "l"(bar) : "memory");
                    if (v >= target) break;
                    __nanosleep(32);
                } while (true);
            }
            __syncthreads();
        }
    }
}

// ---------------- fp32 -> bf16 weight conversion -----------------------------
__global__ void k_conv_w(const float* __restrict__ w) {
    int i = blockIdx.x * 256 + threadIdx.x;
    if (i < VOC * HID / 2) {
        float2 a = ((const float2*)w)[i];
        ((__nv_bfloat162*)g_Wb)[i] = __floats2bfloat162_rn(a.x, a.y);
    }
}

// ---------------- output projection + fused partial logsumexp ----------------
// C tile 128m x 64n per block; emits per-row {max,sumexp} partial + target logit.
__global__ void __launch_bounds__(256) k_out_gemm(const float* __restrict__ bias,
                                                  const int* __restrict__ trg_out) {
    __shared__ int   sTgt[128];
    __shared__ float sMax[2][128];
    __shared__ float sSum[2][128];

    int tid = threadIdx.x;
    int lane = tid & 31, warp = tid >> 5;
    int wm = warp >> 1, wn = warp & 1;
    int nblk = blockIdx.x, mblk = blockIdx.y;
    int rowbase = mblk * 128, n0 = nblk * 64;
    int m_base = rowbase + wm * 32;
    int n_base = n0 + wn * 32;
    int gid = lane >> 2, tg = lane & 3;

    for (int i = tid; i < 128; i += 256) sTgt[i] = trg_out[rowbase + i];
    __syncthreads();

    float c[2][4][4];
#pragma unroll
    for (int mt = 0; mt < 2; mt++)
#pragma unroll
        for (int nt = 0; nt < 4; nt++)
#pragma unroll
            for (int q = 0; q < 4; q++) c[mt][nt][q] = 0.0f;

    for (int k0 = 0; k0 < HID; k0 += 16) {
        uint32_t a[2][4];
#pragma unroll
        for (int mt = 0; mt < 2; mt++) {
            const __nv_bfloat16* ap =
                g_hb + (size_t)(m_base + mt * 16 + gid) * HID + k0 + tg * 2;
            a[mt][0] = *(const uint32_t*)(ap);
            a[mt][1] = *(const uint32_t*)(ap + 8 * HID);
            a[mt][2] = *(const uint32_t*)(ap + 8);
            a[mt][3] = *(const uint32_t*)(ap + 8 * HID + 8);
        }
#pragma unroll
        for (int nt = 0; nt < 4; nt++) {
            const __nv_bfloat16* bp =
                g_Wb + (size_t)(n_base + nt * 8 + gid) * HID + k0 + tg * 2;
            uint32_t b0 = *(const uint32_t*)(bp);
            uint32_t b1 = *(const uint32_t*)(bp + 8);
#pragma unroll
            for (int mt = 0; mt < 2; mt++) {
                asm volatile(
                    "mma.sync.aligned.m16n8k16.row.col.f32.bf16.bf16.f32 "
                    "{%0,%1,%2,%3}, {%4,%5,%6,%7}, {%8,%9}, {%0,%1,%2,%3};"
                    : "+f"(c[mt][nt][0]), "+f"(c[mt][nt][1]),
                      "+f"(c[mt][nt][2]), "+f"(c[mt][nt][3])
                    : "r"(a[mt][0]), "r"(a[mt][1]), "r"(a[mt][2]), "r"(a[mt][3]),
                      "r"(b0), "r"(b1));
            }
        }
    }

    // fold bias into accumulators (cols depend on nt/tg, same for both rows)
#pragma unroll
    for (int nt = 0; nt < 4; nt++) {
        float bv0 = bias[n_base + nt * 8 + tg * 2];
        float bv1 = bias[n_base + nt * 8 + tg * 2 + 1];
#pragma unroll
        for (int mt = 0; mt < 2; mt++) {
            c[mt][nt][0] += bv0; c[mt][nt][1] += bv1;
            c[mt][nt][2] += bv0; c[mt][nt][3] += bv1;
        }
    }

    // phase 1: per-row warp max + target capture
#pragma unroll
    for (int slot = 0; slot < 4; slot++) {
        int mt = slot >> 1, hi = slot & 1;
        int rl = wm * 32 + mt * 16 + gid + hi * 8;
        float ml = -1e30f;
#pragma unroll
        for (int nt = 0; nt < 4; nt++) {
            ml = fmaxf(ml, c[mt][nt][hi * 2]);
            ml = fmaxf(ml, c[mt][nt][hi * 2 + 1]);
        }
        ml = fmaxf(ml, __shfl_xor_sync(0xffffffffu, ml, 1));
        ml = fmaxf(ml, __shfl_xor_sync(0xffffffffu, ml, 2));
        if (tg == 0) sMax[wn][rl] = ml;

        int tl = sTgt[rl] - n0;
        if (tl >= 0 && tl < 64 && (tl >> 5) == wn) {
            int ntt = (tl & 31) >> 3;
            int tgt_tg = (tl & 7) >> 1;
            int qt = tl & 1;
            if (tg == tgt_tg) {
                float val = 0.f;
#pragma unroll
                for (int nt = 0; nt < 4; nt++)
                    if (nt == ntt) val = c[mt][nt][hi * 2 + qt];
                g_tgt[rowbase + rl] = val;
            }
        }
    }
    __syncthreads();

    // phase 2: per-row warp sumexp relative to block row max
#pragma unroll
    for (int slot = 0; slot < 4; slot++) {
        int mt = slot >> 1, hi = slot & 1;
        int rl = wm * 32 + mt * 16 + gid + hi * 8;
        float M = fmaxf(sMax[0][rl], sMax[1][rl]);
        float sl = 0.f;
#pragma unroll
        for (int nt = 0; nt < 4; nt++) {
            sl += __expf(c[mt][nt][hi * 2] - M);
            sl += __expf(c[mt][nt][hi * 2 + 1] - M);
        }
        sl += __shfl_xor_sync(0xffffffffu, sl, 1);
        sl += __shfl_xor_sync(0xffffffffu, sl, 2);
        if (tg == 0) sSum[wn][rl] = sl;
    }
    __syncthreads();

    if (tid < 128) {
        float M = fmaxf(sMax[0][tid], sMax[1][tid]);
        g_part[(size_t)(rowbase + tid) * NBLKS + nblk] =
            make_float2(M, sSum[0][tid] + sSum[1][tid]);
    }
}

// ---------------- combine partials -> per-row NLL ----------------------------
__global__ void k_nll2() {
    int r = blockIdx.x, t = threadIdx.x;
    const float2* pp = g_part + (size_t)r * NBLKS;

    float m = -1e30f, s = 0.0f;
    for (int i = t; i < NBLKS; i += 256) {
        float2 p = pp[i];
        if (p.x > m) { s = s * __expf(m - p.x) + p.y; m = p.x; }
        else s += p.y * __expf(p.x - m);
    }
    __shared__ float sm_[256], ss_[256];
    sm_[t] = m; ss_[t] = s; __syncthreads();
    for (int k = 128; k > 0; k >>= 1) {
        if (t < k) {
            float m2 = sm_[t + k], s2 = ss_[t + k];
            float M = fmaxf(sm_[t], m2);
            ss_[t] = ss_[t] * __expf(sm_[t] - M) + s2 * __expf(m2 - M);
            sm_[t] = M;
        }
        __syncthreads();
    }
    if (t == 0) g_rownll[r] = sm_[0] + logf(ss_[0]) - g_tgt[r];
}

__global__ void k_mean(float* __restrict__ out) {
    __shared__ float red[256];
    int t = threadIdx.x;
    float s = 0.0f;
    for (int i = t; i < BT; i += 256) s += g_rownll[i];
    red[t] = s; __syncthreads();
    for (int k = 128; k > 0; k >>= 1) {
        if (t < k) red[t] += red[t + k];
        __syncthreads();
    }
    if (t == 0) out[0] = red[0] / (float)BT;
}

// ---------------- launch -----------------------------------------------------
extern "C" void kernel_launch(void* const* d_in, const int* in_sizes, int n_in,
                              void* d_out, int out_size) {
    const int*   src      = (const int*)  d_in[0];
    const int*   src_len  = (const int*)  d_in[1];
    const int*   trg_in   = (const int*)  d_in[2];
    const int*   trg_out  = (const int*)  d_in[3];
    const float* src_emb  = (const float*)d_in[4];
    const float* trg_emb  = (const float*)d_in[5];
    const float* enc_Wih  = (const float*)d_in[6];
    const float* enc_Whh  = (const float*)d_in[7];
    const float* enc_bih  = (const float*)d_in[8];
    const float* enc_bhh  = (const float*)d_in[9];
    const float* dec_Wi   = (const float*)d_in[10];
    const float* dec_bi   = (const float*)d_in[11];
    const float* dec_Wh   = (const float*)d_in[12];
    const float* dec_bh   = (const float*)d_in[13];
    const float* dec_Wp   = (const float*)d_in[14];
    const float* dec_bp   = (const float*)d_in[15];
    const float* out_W    = (const float*)d_in[16];
    const float* out_b    = (const float*)d_in[17];
    float* out = (float*)d_out;

    const int SMEMB = (12 * 520 + 32 * 516 + 4 * 384 + 384) * 4;   // 98688 B
    cudaFuncSetAttribute(k_recur<SLEN, false>,
                         cudaFuncAttributeMaxDynamicSharedMemorySize, SMEMB);
    cudaFuncSetAttribute(k_recur<TLEN, true>,
                         cudaFuncAttributeMaxDynamicSharedMemorySize, SMEMB);

    k_reset_bars<<<1, 1>>>();
    k_zero_h0<<<(BATCH * HID + 255) / 256, 256>>>();

    // gx = emb(src) @ Wih^T + bih   [4096 x 1536]
    k_big_gemm<<<dim3(G3 / 64, SB / 64), 256>>>(src_emb, src, SLEN, SB, EMB,
                                                enc_Wih, enc_bih, 0, 0);
    // gi = emb(trg) @ Wi^T + bi     [2048 x 1536]
    k_big_gemm<<<dim3(G3 / 64, BT / 64), 256>>>(trg_emb, trg_in, TLEN, BT, EMB,
                                                dec_Wi, dec_bi, 1, 0);
    // bf16 weights for output projection
    k_conv_w<<<(VOC * HID / 2 + 255) / 256, 256>>>(out_W);

    // encoder: all 128 steps in one persistent kernel
    k_recur<SLEN, false><<<RNBLK, 384, SMEMB>>>(enc_Whh, enc_bhh, src_len);

    // p = ctx @ Wp^T + bp  (ctx = final encoder h in g_h[0])
    k_big_gemm<<<dim3(G3 / 64, 1), 256>>>(nullptr, nullptr, 0, BATCH, HID,
                                          dec_Wp, dec_bp, 2, 1);

    // decoder: all 64 steps in one persistent kernel (writes g_hb bf16)
    k_recur<TLEN, true><<<RNBLK, 384, SMEMB>>>(dec_Wh, dec_bh, nullptr);

    // output projection + fused partial logsumexp, then combine + mean
    k_out_gemm<<<dim3(NBLKS, BT / 128), 256>>>(out_b, trg_out);
    k_nll2<<<BT, 256>>>();
    k_mean<<<1, 256>>>(out);
}

// round 13
// speedup vs baseline: 1.0014x; 1.0014x over previous
#include <cuda_runtime.h>
#include <cuda_bf16.h>
#include <cstdint>

#define BATCH 32
#define SLEN  128
#define TLEN  64
#define VOC   32000
#define EMB   256
#define HID   512
#define G3    1536            // 3*HID
#define BT    (BATCH*TLEN)    // 2048 decoder rows
#define SB    (SLEN*BATCH)    // 4096 encoder rows
#define RNBLK 128             // persistent recurrence blocks (<=148 SMs)
#define NBLKS (VOC/64)        // 500 n-blocks in output projection

// ---------------- scratch (device globals; no allocation allowed) ----------
__device__ float g_gx  [SB*G3];               // [s][b][3H]
__device__ float g_gi  [BT*G3];               // [t][b][3H]
__device__ float g_p   [BATCH*G3];            // ctx @ Wp^T + bp
__device__ float g_h   [2][BATCH*HID];        // hidden ping-pong (enc then dec)
__device__ __nv_bfloat16 g_hb[BT*HID];        // bf16 decoder outputs, row = b*T+t
__device__ __nv_bfloat16 g_Wb[VOC*HID];       // bf16 copy of out_W
__device__ float2 g_part[(size_t)BT*NBLKS];   // per (row, nblk) {max, sumexp}
__device__ float g_tgt[BT];                   // target logit per row (with bias)
__device__ float g_rownll[BT];
__device__ unsigned g_barE, g_barD;

__device__ __forceinline__ float sigf(float x) { return 1.0f / (1.0f + __expf(-x)); }

__global__ void k_reset_bars() { g_barE = 0; g_barD = 0; }

__global__ void k_zero_h0() {
    int i = blockIdx.x * 256 + threadIdx.x;
    if (i < BATCH * HID) g_h[0][i] = 0.0f;
}

// ---------------- input GEMM:  out[m][n] = A_row(m) . W[n][:] + bias[n] -----
__global__ void k_big_gemm(const float* __restrict__ Asrc,
                           const int* __restrict__ ids, int ids_len,
                           int rows, int K,
                           const float* __restrict__ W,
                           const float* __restrict__ bias,
                           int outsel, int a_from_ctx) {
    __shared__ __align__(16) float As[16][72];   // [kk][m]
    __shared__ __align__(16) float Bs[16][72];   // [kk][n]
    __shared__ int sIds[64];

    float* out = (outsel == 0) ? g_gx : (outsel == 1) ? g_gi : g_p;
    const float* Abase = a_from_ctx ? g_h[0] : Asrc;

    int tid = threadIdx.x;                // 256 threads
    int m0 = blockIdx.y * 64, n0 = blockIdx.x * 64;
    int ty = tid / 16, tx = tid % 16;

    if (ids) {
        for (int i = tid; i < 64; i += 256) {
            int m = m0 + i;
            sIds[i] = (m < rows) ? ids[(m % BATCH) * ids_len + (m / BATCH)] : 0;
        }
        __syncthreads();
    }

    float acc[4][4];
#pragma unroll
    for (int i = 0; i < 4; i++)
#pragma unroll
        for (int j = 0; j < 4; j++) acc[i][j] = 0.0f;

    for (int k0 = 0; k0 < K; k0 += 16) {
        for (int i = tid; i < 1024; i += 256) {
            int r = i / 16, kk = i % 16;
            int m = m0 + r;
            float v = 0.0f;
            if (m < rows) {
                const float* ap = ids ? (Abase + (size_t)sIds[r] * K)
                                      : (Abase + (size_t)m * K);
                v = ap[k0 + kk];
            }
            As[kk][r] = v;
        }
        for (int i = tid; i < 1024; i += 256) {
            int n = i / 16, kk = i % 16;
            Bs[kk][n] = W[(size_t)(n0 + n) * K + k0 + kk];
        }
        __syncthreads();
#pragma unroll
        for (int kk = 0; kk < 16; kk++) {
            float4 a4 = *(const float4*)&As[kk][ty * 4];
            float4 b4 = *(const float4*)&Bs[kk][tx * 4];
            float a[4] = {a4.x, a4.y, a4.z, a4.w};
            float b[4] = {b4.x, b4.y, b4.z, b4.w};
#pragma unroll
            for (int i = 0; i < 4; i++)
#pragma unroll
                for (int j = 0; j < 4; j++) acc[i][j] += a[i] * b[j];
        }
        __syncthreads();
    }

#pragma unroll
    for (int i = 0; i < 4; i++) {
        int m = m0 + ty * 4 + i;
        if (m >= rows) continue;
#pragma unroll
        for (int j = 0; j < 4; j++) {
            int n = n0 + tx * 4 + j;
            out[(size_t)m * G3 + n] = acc[i][j] + bias[n];
        }
    }
}

// ---------------- persistent recurrence v2 ----------------------------------
// 128 blocks x 384 thr (12 warps). Block owns 4 h-cols (12 gate cols).
// Dot: warp = (col-group cw of 4 cols, k-chunk kc of 128); lane = (cl, o),
// computes 4 batch outputs (o, o+8, o+16, o+24). Partials reduced via smem.
// Grid barrier: single-thread release/acquire atomics.
template<int STEPS, bool DEC>
__global__ void __launch_bounds__(384, 1)
k_recur(const float* __restrict__ Wrec,   // [G3][HID] row-major
        const float* __restrict__ brec,   // [G3]
        const int* __restrict__ src_len)  // encoder only
{
    extern __shared__ float sm[];
    float* Wsm = sm;                       // 12*520
    float* hsm = Wsm + 12 * 520;           // 32*516
    float* red = hsm + 32 * 516;           // 4*384 partials
    float* ghm = red + 4 * 384;            // 384 reduced gates

    const int t = threadIdx.x;
    const int j0 = blockIdx.x * 4;

    // cache weight slice (12 gate rows x 512) in smem, padded to 520
    for (int i = t; i < 12 * 512; i += 384) {
        int gc = i >> 9, k = i & 511;
        Wsm[gc * 520 + k] = Wrec[(size_t)((gc >> 2) * 512 + j0 + (gc & 3)) * 512 + k];
    }

    // dot-role constants
    const int w  = t >> 5;                 // warp 0..11
    const int kc = w & 3;                  // k-chunk
    const int cw = w >> 2;                 // col-group 0..2
    const int lane = t & 31;
    const int cl = lane >> 3, o = lane & 7;
    const int gc_d = cw * 4 + cl;

    // reduce-role constants
    const int gc_r = t >> 5;               // 0..11
    const int b_r  = t & 31;
    const float biasr = brec[(gc_r >> 2) * 512 + j0 + (gc_r & 3)];

    // combine-role constants (t < 128)
    const int hc = t >> 5, bc = t & 31;    // valid when t<128
    const int jc = j0 + hc;
    float p0 = 0.f, p1 = 0.f, p2 = 0.f;
    int slen = 0;
    if (t < 128) {
        if (DEC) {
            p0 = g_p[bc * G3 + jc];
            p1 = g_p[bc * G3 + 512 + jc];
            p2 = g_p[bc * G3 + 1024 + jc];
        } else {
            slen = src_len[bc];
        }
    }
    __syncthreads();

    unsigned* bar = DEC ? &g_barD : &g_barE;
    const float* gbase = DEC ? g_gi : g_gx;

    for (int s = 0; s < STEPS; s++) {
        const float* hprev = g_h[s & 1];
        float* hnext = g_h[(s + 1) & 1];

        // prefetch this step's input-gate values (used in combine)
        float gx0 = 0.f, gx1 = 0.f, gx2 = 0.f;
        if (t < 128) {
            const float* gr = gbase + ((size_t)s * BATCH + bc) * G3;
            gx0 = gr[jc]; gx1 = gr[512 + jc]; gx2 = gr[1024 + jc];
        }

        // stage h[32][512] to smem
        for (int f = t; f < 4096; f += 384) {
            int b = f >> 7, kq = f & 127;
            float4 v = __ldcg((const float4*)(hprev + b * 512 + kq * 4));
            *(float4*)(hsm + b * 516 + kq * 4) = v;
        }
        __syncthreads();

        // dot partials: 4 batches per lane over a 128-k chunk
        {
            const float* wp = Wsm + gc_d * 520 + kc * 128;
            const float* h0 = hsm + (o     ) * 516 + kc * 128;
            const float* h1 = hsm + (o +  8) * 516 + kc * 128;
            const float* h2 = hsm + (o + 16) * 516 + kc * 128;
            const float* h3 = hsm + (o + 24) * 516 + kc * 128;
            float a0 = 0.f, a1 = 0.f, a2 = 0.f, a3 = 0.f;
#pragma unroll 8
            for (int k = 0; k < 128; k += 4) {
                float4 wv = *(const float4*)(wp + k);
                float4 v0 = *(const float4*)(h0 + k);
                float4 v1 = *(const float4*)(h1 + k);
                float4 v2 = *(const float4*)(h2 + k);
                float4 v3 = *(const float4*)(h3 + k);
                a0 += wv.x * v0.x + wv.y * v0.y + wv.z * v0.z + wv.w * v0.w;
                a1 += wv.x * v1.x + wv.y * v1.y + wv.z * v1.z + wv.w * v1.w;
                a2 += wv.x * v2.x + wv.y * v2.y + wv.z * v2.z + wv.w * v2.w;
                a3 += wv.x * v3.x + wv.y * v3.y + wv.z * v3.z + wv.w * v3.w;
            }
            float* rp = red + kc * 384 + gc_d * 32;
            rp[o] = a0; rp[o + 8] = a1; rp[o + 16] = a2; rp[o + 24] = a3;
        }
        __syncthreads();

        // reduce 4 k-chunks + bias
        ghm[gc_r * 32 + b_r] = red[gc_r * 32 + b_r] + red[384 + gc_r * 32 + b_r]
                             + red[768 + gc_r * 32 + b_r] + red[1152 + gc_r * 32 + b_r]
                             + biasr;
        __syncthreads();

        // combine gates + write new h
        if (t < 128) {
            float ghr = ghm[hc * 32 + bc];
            float ghz = ghm[(4 + hc) * 32 + bc];
            float ghn = ghm[(8 + hc) * 32 + bc];
            float hold = hsm[bc * 516 + jc];
            float hy;
            if (DEC) {
                float r  = sigf(gx0 + ghr + p0);
                float ig = sigf(gx1 + ghz + p1);
                float nn = tanhf(gx2 + r * ghn + p2);
                hy = nn + ig * (hold - nn);
                g_hb[((size_t)bc * TLEN + s) * HID + jc] = __float2bfloat16(hy);
            } else {
                float r  = sigf(gx0 + ghr);
                float z  = sigf(gx1 + ghz);
                float nn = tanhf(gx2 + r * ghn);
                float hn = (1.0f - z) * nn + z * hold;
                hy = (s < slen) ? hn : hold;
            }
            __stcg(hnext + bc * 512 + jc, hy);
        }

        // grid barrier (release/acquire, single thread)
        if (s + 1 < STEPS) {
            __syncthreads();
            if (t == 0) {
                asm volatile("red.release.gpu.global.add.u32 [%0], %1;"
                             :: "l"(bar), "r"(1u) : "memory");
                unsigned target = (unsigned)(s + 1) * RNBLK;
                unsigned v;
                do {
                    asm volatile("ld.acquire.gpu.global.u32 %0, [%1];"
                                 : "=r"(v) : "l"(bar) : "memory");
                    if (v >= target) break;
                    __nanosleep(32);
                } while (true);
            }
            __syncthreads();
        }
    }
}

// ---------------- fp32 -> bf16 weight conversion -----------------------------
__global__ void k_conv_w(const float* __restrict__ w) {
    int i = blockIdx.x * 256 + threadIdx.x;
    if (i < VOC * HID / 2) {
        float2 a = ((const float2*)w)[i];
        ((__nv_bfloat162*)g_Wb)[i] = __floats2bfloat162_rn(a.x, a.y);
    }
}

// ---------------- output projection + fused partial logsumexp ----------------
// C tile 128m x 64n per block; emits per-row {max,sumexp} partial + target logit.
__global__ void __launch_bounds__(256) k_out_gemm(const float* __restrict__ bias,
                                                  const int* __restrict__ trg_out) {
    __shared__ int   sTgt[128];
    __shared__ float sMax[2][128];
    __shared__ float sSum[2][128];

    int tid = threadIdx.x;
    int lane = tid & 31, warp = tid >> 5;
    int wm = warp >> 1, wn = warp & 1;
    int nblk = blockIdx.x, mblk = blockIdx.y;
    int rowbase = mblk * 128, n0 = nblk * 64;
    int m_base = rowbase + wm * 32;
    int n_base = n0 + wn * 32;
    int gid = lane >> 2, tg = lane & 3;

    for (int i = tid; i < 128; i += 256) sTgt[i] = trg_out[rowbase + i];
    __syncthreads();

    float c[2][4][4];
#pragma unroll
    for (int mt = 0; mt < 2; mt++)
#pragma unroll
        for (int nt = 0; nt < 4; nt++)
#pragma unroll
            for (int q = 0; q < 4; q++) c[mt][nt][q] = 0.0f;

    for (int k0 = 0; k0 < HID; k0 += 16) {
        uint32_t a[2][4];
#pragma unroll
        for (int mt = 0; mt < 2; mt++) {
            const __nv_bfloat16* ap =
                g_hb + (size_t)(m_base + mt * 16 + gid) * HID + k0 + tg * 2;
            a[mt][0] = *(const uint32_t*)(ap);
            a[mt][1] = *(const uint32_t*)(ap + 8 * HID);
            a[mt][2] = *(const uint32_t*)(ap + 8);
            a[mt][3] = *(const uint32_t*)(ap + 8 * HID + 8);
        }
#pragma unroll
        for (int nt = 0; nt < 4; nt++) {
            const __nv_bfloat16* bp =
                g_Wb + (size_t)(n_base + nt * 8 + gid) * HID + k0 + tg * 2;
            uint32_t b0 = *(const uint32_t*)(bp);
            uint32_t b1 = *(const uint32_t*)(bp + 8);
#pragma unroll
            for (int mt = 0; mt < 2; mt++) {
                asm volatile(
                    "mma.sync.aligned.m16n8k16.row.col.f32.bf16.bf16.f32 "
                    "{%0,%1,%2,%3}, {%4,%5,%6,%7}, {%8,%9}, {%0,%1,%2,%3};"
                    : "+f"(c[mt][nt][0]), "+f"(c[mt][nt][1]),
                      "+f"(c[mt][nt][2]), "+f"(c[mt][nt][3])
                    : "r"(a[mt][0]), "r"(a[mt][1]), "r"(a[mt][2]), "r"(a[mt][3]),
                      "r"(b0), "r"(b1));
            }
        }
    }

    // fold bias into accumulators (cols depend on nt/tg, same for both rows)
#pragma unroll
    for (int nt = 0; nt < 4; nt++) {
        float bv0 = bias[n_base + nt * 8 + tg * 2];
        float bv1 = bias[n_base + nt * 8 + tg * 2 + 1];
#pragma unroll
        for (int mt = 0; mt < 2; mt++) {
            c[mt][nt][0] += bv0; c[mt][nt][1] += bv1;
            c[mt][nt][2] += bv0; c[mt][nt][3] += bv1;
        }
    }

    // phase 1: per-row warp max + target capture
#pragma unroll
    for (int slot = 0; slot < 4; slot++) {
        int mt = slot >> 1, hi = slot & 1;
        int rl = wm * 32 + mt * 16 + gid + hi * 8;
        float ml = -1e30f;
#pragma unroll
        for (int nt = 0; nt < 4; nt++) {
            ml = fmaxf(ml, c[mt][nt][hi * 2]);
            ml = fmaxf(ml, c[mt][nt][hi * 2 + 1]);
        }
        ml = fmaxf(ml, __shfl_xor_sync(0xffffffffu, ml, 1));
        ml = fmaxf(ml, __shfl_xor_sync(0xffffffffu, ml, 2));
        if (tg == 0) sMax[wn][rl] = ml;

        int tl = sTgt[rl] - n0;
        if (tl >= 0 && tl < 64 && (tl >> 5) == wn) {
            int ntt = (tl & 31) >> 3;
            int tgt_tg = (tl & 7) >> 1;
            int qt = tl & 1;
            if (tg == tgt_tg) {
                float val = 0.f;
#pragma unroll
                for (int nt = 0; nt < 4; nt++)
                    if (nt == ntt) val = c[mt][nt][hi * 2 + qt];
                g_tgt[rowbase + rl] = val;
            }
        }
    }
    __syncthreads();

    // phase 2: per-row warp sumexp relative to block row max
#pragma unroll
    for (int slot = 0; slot < 4; slot++) {
        int mt = slot >> 1, hi = slot & 1;
        int rl = wm * 32 + mt * 16 + gid + hi * 8;
        float M = fmaxf(sMax[0][rl], sMax[1][rl]);
        float sl = 0.f;
#pragma unroll
        for (int nt = 0; nt < 4; nt++) {
            sl += __expf(c[mt][nt][hi * 2] - M);
            sl += __expf(c[mt][nt][hi * 2 + 1] - M);
        }
        sl += __shfl_xor_sync(0xffffffffu, sl, 1);
        sl += __shfl_xor_sync(0xffffffffu, sl, 2);
        if (tg == 0) sSum[wn][rl] = sl;
    }
    __syncthreads();

    if (tid < 128) {
        float M = fmaxf(sMax[0][tid], sMax[1][tid]);
        g_part[(size_t)(rowbase + tid) * NBLKS + nblk] =
            make_float2(M, sSum[0][tid] + sSum[1][tid]);
    }
}

// ---------------- combine partials -> per-row NLL ----------------------------
__global__ void k_nll2() {
    int r = blockIdx.x, t = threadIdx.x;
    const float2* pp = g_part + (size_t)r * NBLKS;

    float m = -1e30f, s = 0.0f;
    for (int i = t; i < NBLKS; i += 256) {
        float2 p = pp[i];
        if (p.x > m) { s = s * __expf(m - p.x) + p.y; m = p.x; }
        else s += p.y * __expf(p.x - m);
    }
    __shared__ float sm_[256], ss_[256];
    sm_[t] = m; ss_[t] = s; __syncthreads();
    for (int k = 128; k > 0; k >>= 1) {
        if (t < k) {
            float m2 = sm_[t + k], s2 = ss_[t + k];
            float M = fmaxf(sm_[t], m2);
            ss_[t] = ss_[t] * __expf(sm_[t] - M) + s2 * __expf(m2 - M);
            sm_[t] = M;
        }
        __syncthreads();
    }
    if (t == 0) g_rownll[r] = sm_[0] + logf(ss_[0]) - g_tgt[r];
}

__global__ void k_mean(float* __restrict__ out) {
    __shared__ float red[256];
    int t = threadIdx.x;
    float s = 0.0f;
    for (int i = t; i < BT; i += 256) s += g_rownll[i];
    red[t] = s; __syncthreads();
    for (int k = 128; k > 0; k >>= 1) {
        if (t < k) red[t] += red[t + k];
        __syncthreads();
    }
    if (t == 0) out[0] = red[0] / (float)BT;
}

// ---------------- launch -----------------------------------------------------
extern "C" void kernel_launch(void* const* d_in, const int* in_sizes, int n_in,
                              void* d_out, int out_size) {
    const int*   src      = (const int*)  d_in[0];
    const int*   src_len  = (const int*)  d_in[1];
    const int*   trg_in   = (const int*)  d_in[2];
    const int*   trg_out  = (const int*)  d_in[3];
    const float* src_emb  = (const float*)d_in[4];
    const float* trg_emb  = (const float*)d_in[5];
    const float* enc_Wih  = (const float*)d_in[6];
    const float* enc_Whh  = (const float*)d_in[7];
    const float* enc_bih  = (const float*)d_in[8];
    const float* enc_bhh  = (const float*)d_in[9];
    const float* dec_Wi   = (const float*)d_in[10];
    const float* dec_bi   = (const float*)d_in[11];
    const float* dec_Wh   = (const float*)d_in[12];
    const float* dec_bh   = (const float*)d_in[13];
    const float* dec_Wp   = (const float*)d_in[14];
    const float* dec_bp   = (const float*)d_in[15];
    const float* out_W    = (const float*)d_in[16];
    const float* out_b    = (const float*)d_in[17];
    float* out = (float*)d_out;

    const int SMEMB = (12 * 520 + 32 * 516 + 4 * 384 + 384) * 4;   // 98688 B
    cudaFuncSetAttribute(k_recur<SLEN, false>,
                         cudaFuncAttributeMaxDynamicSharedMemorySize, SMEMB);
    cudaFuncSetAttribute(k_recur<TLEN, true>,
                         cudaFuncAttributeMaxDynamicSharedMemorySize, SMEMB);

    k_reset_bars<<<1, 1>>>();
    k_zero_h0<<<(BATCH * HID + 255) / 256, 256>>>();

    // gx = emb(src) @ Wih^T + bih   [4096 x 1536]
    k_big_gemm<<<dim3(G3 / 64, SB / 64), 256>>>(src_emb, src, SLEN, SB, EMB,
                                                enc_Wih, enc_bih, 0, 0);
    // gi = emb(trg) @ Wi^T + bi     [2048 x 1536]
    k_big_gemm<<<dim3(G3 / 64, BT / 64), 256>>>(trg_emb, trg_in, TLEN, BT, EMB,
                                                dec_Wi, dec_bi, 1, 0);
    // bf16 weights for output projection
    k_conv_w<<<(VOC * HID / 2 + 255) / 256, 256>>>(out_W);

    // encoder: all 128 steps in one persistent kernel
    k_recur<SLEN, false><<<RNBLK, 384, SMEMB>>>(enc_Whh, enc_bhh, src_len);

    // p = ctx @ Wp^T + bp  (ctx = final encoder h in g_h[0])
    k_big_gemm<<<dim3(G3 / 64, 1), 256>>>(nullptr, nullptr, 0, BATCH, HID,
                                          dec_Wp, dec_bp, 2, 1);

    // decoder: all 64 steps in one persistent kernel (writes g_hb bf16)
    k_recur<TLEN, true><<<RNBLK, 384, SMEMB>>>(dec_Wh, dec_bh, nullptr);

    // output projection + fused partial logsumexp, then combine + mean
    k_out_gemm<<<dim3(NBLKS, BT / 128), 256>>>(out_b, trg_out);
    k_nll2<<<BT, 256>>>();
    k_mean<<<1, 256>>>(out);
}

// round 15
// speedup vs baseline: 1.1629x; 1.1613x over previous
#include <cuda_runtime.h>
#include <cuda_bf16.h>
#include <cstdint>

#define BATCH 32
#define SLEN  128
#define TLEN  64
#define VOC   32000
#define EMB   256
#define HID   512
#define G3    1536            // 3*HID
#define BT    (BATCH*TLEN)    // 2048 decoder rows
#define SB    (SLEN*BATCH)    // 4096 encoder rows
#define RNBLK 128             // persistent recurrence blocks (<=148 SMs)
#define NBLKS (VOC/64)        // 500 n-blocks in output projection

// ---------------- scratch (device globals; no allocation allowed) ----------
__device__ float g_gx  [SB*G3];               // [s][b][3H]
__device__ float g_gi  [BT*G3];               // [t][b][3H]
__device__ float g_p   [BATCH*G3];            // ctx @ Wp^T + bp
__device__ float g_h   [2][BATCH*HID];        // hidden ping-pong (enc then dec)
__device__ __nv_bfloat16 g_hb[BT*HID];        // bf16 decoder outputs, row = b*T+t
__device__ __nv_bfloat16 g_Wb[VOC*HID];       // bf16 copy of out_W
__device__ float2 g_part[(size_t)BT*NBLKS];   // per (row, nblk) {max, sumexp}
__device__ float g_tgt[BT];                   // target logit per row (with bias)
__device__ float g_rownll[BT];
__device__ unsigned g_barE, g_barD;

__device__ __forceinline__ float sigf(float x) { return 1.0f / (1.0f + __expf(-x)); }

__global__ void k_reset_bars() { g_barE = 0; g_barD = 0; }

__global__ void k_zero_h0() {
    int i = blockIdx.x * 256 + threadIdx.x;
    if (i < BATCH * HID) g_h[0][i] = 0.0f;
}

// ---------------- input GEMM:  out[m][n] = A_row(m) . W[n][:] + bias[n] -----
// 128m x 64n tile, 256 threads, 8x4 per thread.
__global__ void __launch_bounds__(256) k_big_gemm(
        const float* __restrict__ Asrc,
        const int* __restrict__ ids, int ids_len,
        int rows, int K,
        const float* __restrict__ W,
        const float* __restrict__ bias,
        int outsel, int a_from_ctx) {
    __shared__ __align__(16) float As[16][136];  // [kk][m]
    __shared__ __align__(16) float Bs[16][72];   // [kk][n]
    __shared__ int sIds[128];

    float* out = (outsel == 0) ? g_gx : (outsel == 1) ? g_gi : g_p;
    const float* Abase = a_from_ctx ? g_h[0] : Asrc;

    int tid = threadIdx.x;
    int m0 = blockIdx.y * 128, n0 = blockIdx.x * 64;
    int ty = tid >> 4, tx = tid & 15;            // ty: 8 rows, tx: 4 cols

    if (ids) {
        for (int i = tid; i < 128; i += 256) {
            int m = m0 + i;
            sIds[i] = (m < rows) ? ids[(m % BATCH) * ids_len + (m / BATCH)] : 0;
        }
        __syncthreads();
    }

    float acc[8][4];
#pragma unroll
    for (int i = 0; i < 8; i++)
#pragma unroll
        for (int j = 0; j < 4; j++) acc[i][j] = 0.0f;

    for (int k0 = 0; k0 < K; k0 += 16) {
        for (int i = tid; i < 2048; i += 256) {
            int r = i >> 4, kk = i & 15;
            int m = m0 + r;
            float v = 0.0f;
            if (m < rows) {
                const float* ap = ids ? (Abase + (size_t)sIds[r] * K)
                                      : (Abase + (size_t)m * K);
                v = ap[k0 + kk];
            }
            As[kk][r] = v;
        }
        for (int i = tid; i < 1024; i += 256) {
            int n = i >> 4, kk = i & 15;
            Bs[kk][n] = W[(size_t)(n0 + n) * K + k0 + kk];
        }
        __syncthreads();
#pragma unroll
        for (int kk = 0; kk < 16; kk++) {
            float4 a0 = *(const float4*)&As[kk][ty * 8];
            float4 a1 = *(const float4*)&As[kk][ty * 8 + 4];
            float4 b4 = *(const float4*)&Bs[kk][tx * 4];
            float a[8] = {a0.x, a0.y, a0.z, a0.w, a1.x, a1.y, a1.z, a1.w};
            float b[4] = {b4.x, b4.y, b4.z, b4.w};
#pragma unroll
            for (int i = 0; i < 8; i++)
#pragma unroll
                for (int j = 0; j < 4; j++) acc[i][j] += a[i] * b[j];
        }
        __syncthreads();
    }

#pragma unroll
    for (int i = 0; i < 8; i++) {
        int m = m0 + ty * 8 + i;
        if (m >= rows) continue;
#pragma unroll
        for (int j = 0; j < 4; j++) {
            int n = n0 + tx * 4 + j;
            out[(size_t)m * G3 + n] = acc[i][j] + bias[n];
        }
    }
}

// ---------------- persistent recurrence v3 (tensor-core dot) ----------------
// 128 blocks x 256 thr. Block owns 4 h-cols (12 gate cols, padded to 16).
// gh[32][16] = h[32x512] @ Wslice^T via mma.sync bf16x3 (hi/lo split, ~fp32).
// 8 warps = (mt in 2) x (nt in 2) x (ks in 2 k-halves); partials reduced in smem.
template<int STEPS, bool DEC>
__global__ void __launch_bounds__(256, 1)
k_recur(const float* __restrict__ Wrec,   // [G3][HID] row-major
        const float* __restrict__ brec,   // [G3]
        const int* __restrict__ src_len)  // encoder only
{
    extern __shared__ char smraw[];
    __nv_bfloat16* Whi = (__nv_bfloat16*)smraw;       // [16][520]
    __nv_bfloat16* Wlo = Whi + 16 * 520;              // [16][520]
    __nv_bfloat16* Hhi = Wlo + 16 * 520;              // [32][520]
    __nv_bfloat16* Hlo = Hhi + 32 * 520;              // [32][520]
    float* red   = (float*)(Hlo + 32 * 520);          // [2][32][18]
    float* holds = red + 2 * 32 * 18;                 // [32][4] fp32 h_old

    const int t = threadIdx.x;
    const int j0 = blockIdx.x * 4;

    // W slice -> smem bf16 hi/lo. smem rows 0..11 real, 12..15 zero.
    for (int i = t; i < 16 * 512; i += 256) {
        int c = i >> 9, k = i & 511;
        float w = 0.0f;
        if (c < 12) w = Wrec[(size_t)((c >> 2) * 512 + j0 + (c & 3)) * 512 + k];
        __nv_bfloat16 hi = __float2bfloat16(w);
        Whi[c * 520 + k] = hi;
        Wlo[c * 520 + k] = __float2bfloat16(w - __bfloat162float(hi));
    }

    // MMA roles
    const int wid = t >> 5, lane = t & 31;
    const int mt = wid & 1, nt = (wid >> 1) & 1, ks = wid >> 2;
    const int gid = lane >> 2, tg = lane & 3;

    // combine roles (t < 128)
    const int hc = t >> 5, bc = t & 31;
    const int jc = j0 + hc;
    float b0c = 0.f, b1c = 0.f, b2c = 0.f, p0 = 0.f, p1 = 0.f, p2 = 0.f;
    int slen = 0;
    if (t < 128) {
        b0c = brec[jc]; b1c = brec[512 + jc]; b2c = brec[1024 + jc];
        if (DEC) {
            p0 = g_p[bc * G3 + jc];
            p1 = g_p[bc * G3 + 512 + jc];
            p2 = g_p[bc * G3 + 1024 + jc];
        } else {
            slen = src_len[bc];
        }
    }
    __syncthreads();

    unsigned* bar = DEC ? &g_barD : &g_barE;
    const float* gbase = DEC ? g_gi : g_gx;

    for (int s = 0; s < STEPS; s++) {
        const float* hprev = g_h[s & 1];
        float* hnext = g_h[(s + 1) & 1];

        float gx0 = 0.f, gx1 = 0.f, gx2 = 0.f;
        if (t < 128) {
            const float* gr = gbase + ((size_t)s * BATCH + bc) * G3;
            gx0 = gr[jc]; gx1 = gr[512 + jc]; gx2 = gr[1024 + jc];
        }

        // stage h: fp32 -> bf16 hi/lo in smem (+ exact fp32 for owned cols)
        // 32 batches x 128 float4-chunks = 4096 items
        for (int f = t; f < 4096; f += 256) {
            int b = f >> 7, kq = f & 127;
            float4 v = __ldcg((const float4*)(hprev + b * 512 + kq * 4));
            __nv_bfloat162 h01 = __floats2bfloat162_rn(v.x, v.y);
            __nv_bfloat162 h23 = __floats2bfloat162_rn(v.z, v.w);
            __nv_bfloat162 l01 = __floats2bfloat162_rn(v.x - __low2float(h01),
                                                       v.y - __high2float(h01));
            __nv_bfloat162 l23 = __floats2bfloat162_rn(v.z - __low2float(h23),
                                                       v.w - __high2float(h23));
            __nv_bfloat162* ph = (__nv_bfloat162*)(Hhi + b * 520 + kq * 4);
            ph[0] = h01; ph[1] = h23;
            __nv_bfloat162* pl = (__nv_bfloat162*)(Hlo + b * 520 + kq * 4);
            pl[0] = l01; pl[1] = l23;
            if (kq == (j0 >> 2)) {
                holds[b * 4 + 0] = v.x; holds[b * 4 + 1] = v.y;
                holds[b * 4 + 2] = v.z; holds[b * 4 + 3] = v.w;
            }
        }
        __syncthreads();

        // MMA: C[16x8] partial over half-K, 3 passes (hi*hi, hi*lo, lo*hi)
        {
            float c0 = 0.f, c1 = 0.f, c2 = 0.f, c3 = 0.f;
            const int kbase = ks * 256;
            const __nv_bfloat16* A0h = Hhi + (mt * 16 + gid) * 520;
            const __nv_bfloat16* A1h = A0h + 8 * 520;
            const __nv_bfloat16* A0l = Hlo + (mt * 16 + gid) * 520;
            const __nv_bfloat16* A1l = A0l + 8 * 520;
            const __nv_bfloat16* B0h = Whi + (nt * 8 + gid) * 520;
            const __nv_bfloat16* B0l = Wlo + (nt * 8 + gid) * 520;
#pragma unroll 4
            for (int ki = 0; ki < 16; ki++) {
                int k0 = kbase + ki * 16 + tg * 2;
                uint32_t ah0 = *(const uint32_t*)(A0h + k0);
                uint32_t ah1 = *(const uint32_t*)(A1h + k0);
                uint32_t ah2 = *(const uint32_t*)(A0h + k0 + 8);
                uint32_t ah3 = *(const uint32_t*)(A1h + k0 + 8);
                uint32_t al0 = *(const uint32_t*)(A0l + k0);
                uint32_t al1 = *(const uint32_t*)(A1l + k0);
                uint32_t al2 = *(const uint32_t*)(A0l + k0 + 8);
                uint32_t al3 = *(const uint32_t*)(A1l + k0 + 8);
                uint32_t bh0 = *(const uint32_t*)(B0h + k0);
                uint32_t bh1 = *(const uint32_t*)(B0h + k0 + 8);
                uint32_t bl0 = *(const uint32_t*)(B0l + k0);
                uint32_t bl1 = *(const uint32_t*)(B0l + k0 + 8);
#define MMA4(a0,a1,a2,a3,b0,b1) \
    asm volatile("mma.sync.aligned.m16n8k16.row.col.f32.bf16.bf16.f32 " \
                 "{%0,%1,%2,%3}, {%4,%5,%6,%7}, {%8,%9}, {%0,%1,%2,%3};" \
                 : "+f"(c0), "+f"(c1), "+f"(c2), "+f"(c3) \
                 : "r"(a0), "r"(a1), "r"(a2), "r"(a3), "r"(b0), "r"(b1))
                MMA4(ah0, ah1, ah2, ah3, bh0, bh1);
                MMA4(ah0, ah1, ah2, ah3, bl0, bl1);
                MMA4(al0, al1, al2, al3, bh0, bh1);
#undef MMA4
            }
            float* rp0 = red + ks * 576 + (mt * 16 + gid) * 18 + nt * 8 + tg * 2;
            float* rp1 = rp0 + 8 * 18;
            rp0[0] = c0; rp0[1] = c1;
            rp1[0] = c2; rp1[1] = c3;
        }
        __syncthreads();

        // combine gates + write new h
        if (t < 128) {
            const float* r0 = red + bc * 18;
            const float* r1 = red + 576 + bc * 18;
            float ghr = r0[hc]     + r1[hc]     + b0c;
            float ghz = r0[4 + hc] + r1[4 + hc] + b1c;
            float ghn = r0[8 + hc] + r1[8 + hc] + b2c;
            float hold = holds[bc * 4 + hc];
            float hy;
            if (DEC) {
                float r  = sigf(gx0 + ghr + p0);
                float ig = sigf(gx1 + ghz + p1);
                float nn = tanhf(gx2 + r * ghn + p2);
                hy = nn + ig * (hold - nn);
                g_hb[((size_t)bc * TLEN + s) * HID + jc] = __float2bfloat16(hy);
            } else {
                float r  = sigf(gx0 + ghr);
                float z  = sigf(gx1 + ghz);
                float nn = tanhf(gx2 + r * ghn);
                float hn = (1.0f - z) * nn + z * hold;
                hy = (s < slen) ? hn : hold;
            }
            __stcg(hnext + bc * 512 + jc, hy);
        }

        // grid barrier (release/acquire, single thread, tight spin)
        if (s + 1 < STEPS) {
            __syncthreads();
            if (t == 0) {
                asm volatile("red.release.gpu.global.add.u32 [%0], %1;"
                             :: "l"(bar), "r"(1u) : "memory");
                unsigned target = (unsigned)(s + 1) * RNBLK;
                unsigned v;
                do {
                    asm volatile("ld.acquire.gpu.global.u32 %0, [%1];"
                                 : "=r"(v) : "l"(bar) : "memory");
                } while (v < target);
            }
            __syncthreads();
        }
    }
}

// ---------------- fp32 -> bf16 weight conversion -----------------------------
__global__ void k_conv_w(const float* __restrict__ w) {
    int i = blockIdx.x * 256 + threadIdx.x;
    if (i < VOC * HID / 2) {
        float2 a = ((const float2*)w)[i];
        ((__nv_bfloat162*)g_Wb)[i] = __floats2bfloat162_rn(a.x, a.y);
    }
}

// ---------------- output projection + fused partial logsumexp ----------------
__global__ void __launch_bounds__(256) k_out_gemm(const float* __restrict__ bias,
                                                  const int* __restrict__ trg_out) {
    __shared__ int   sTgt[128];
    __shared__ float sMax[2][128];
    __shared__ float sSum[2][128];

    int tid = threadIdx.x;
    int lane = tid & 31, warp = tid >> 5;
    int wm = warp >> 1, wn = warp & 1;
    int nblk = blockIdx.x, mblk = blockIdx.y;
    int rowbase = mblk * 128, n0 = nblk * 64;
    int m_base = rowbase + wm * 32;
    int n_base = n0 + wn * 32;
    int gid = lane >> 2, tg = lane & 3;

    for (int i = tid; i < 128; i += 256) sTgt[i] = trg_out[rowbase + i];
    __syncthreads();

    float c[2][4][4];
#pragma unroll
    for (int mt = 0; mt < 2; mt++)
#pragma unroll
        for (int nt = 0; nt < 4; nt++)
#pragma unroll
            for (int q = 0; q < 4; q++) c[mt][nt][q] = 0.0f;

    for (int k0 = 0; k0 < HID; k0 += 16) {
        uint32_t a[2][4];
#pragma unroll
        for (int mt = 0; mt < 2; mt++) {
            const __nv_bfloat16* ap =
                g_hb + (size_t)(m_base + mt * 16 + gid) * HID + k0 + tg * 2;
            a[mt][0] = *(const uint32_t*)(ap);
            a[mt][1] = *(const uint32_t*)(ap + 8 * HID);
            a[mt][2] = *(const uint32_t*)(ap + 8);
            a[mt][3] = *(const uint32_t*)(ap + 8 * HID + 8);
        }
#pragma unroll
        for (int nt = 0; nt < 4; nt++) {
            const __nv_bfloat16* bp =
                g_Wb + (size_t)(n_base + nt * 8 + gid) * HID + k0 + tg * 2;
            uint32_t b0 = *(const uint32_t*)(bp);
            uint32_t b1 = *(const uint32_t*)(bp + 8);
#pragma unroll
            for (int mt = 0; mt < 2; mt++) {
                asm volatile(
                    "mma.sync.aligned.m16n8k16.row.col.f32.bf16.bf16.f32 "
                    "{%0,%1,%2,%3}, {%4,%5,%6,%7}, {%8,%9}, {%0,%1,%2,%3};"
                    : "+f"(c[mt][nt][0]), "+f"(c[mt][nt][1]),
                      "+f"(c[mt][nt][2]), "+f"(c[mt][nt][3])
                    : "r"(a[mt][0]), "r"(a[mt][1]), "r"(a[mt][2]), "r"(a[mt][3]),
                      "r"(b0), "r"(b1));
            }
        }
    }

#pragma unroll
    for (int nt = 0; nt < 4; nt++) {
        float bv0 = bias[n_base + nt * 8 + tg * 2];
        float bv1 = bias[n_base + nt * 8 + tg * 2 + 1];
#pragma unroll
        for (int mt = 0; mt < 2; mt++) {
            c[mt][nt][0] += bv0; c[mt][nt][1] += bv1;
            c[mt][nt][2] += bv0; c[mt][nt][3] += bv1;
        }
    }

#pragma unroll
    for (int slot = 0; slot < 4; slot++) {
        int mt = slot >> 1, hi = slot & 1;
        int rl = wm * 32 + mt * 16 + gid + hi * 8;
        float ml = -1e30f;
#pragma unroll
        for (int nt = 0; nt < 4; nt++) {
            ml = fmaxf(ml, c[mt][nt][hi * 2]);
            ml = fmaxf(ml, c[mt][nt][hi * 2 + 1]);
        }
        ml = fmaxf(ml, __shfl_xor_sync(0xffffffffu, ml, 1));
        ml = fmaxf(ml, __shfl_xor_sync(0xffffffffu, ml, 2));
        if (tg == 0) sMax[wn][rl] = ml;

        int tl = sTgt[rl] - n0;
        if (tl >= 0 && tl < 64 && (tl >> 5) == wn) {
            int ntt = (tl & 31) >> 3;
            int tgt_tg = (tl & 7) >> 1;
            int qt = tl & 1;
            if (tg == tgt_tg) {
                float val = 0.f;
#pragma unroll
                for (int nt = 0; nt < 4; nt++)
                    if (nt == ntt) val = c[mt][nt][hi * 2 + qt];
                g_tgt[rowbase + rl] = val;
            }
        }
    }
    __syncthreads();

#pragma unroll
    for (int slot = 0; slot < 4; slot++) {
        int mt = slot >> 1, hi = slot & 1;
        int rl = wm * 32 + mt * 16 + gid + hi * 8;
        float M = fmaxf(sMax[0][rl], sMax[1][rl]);
        float sl = 0.f;
#pragma unroll
        for (int nt = 0; nt < 4; nt++) {
            sl += __expf(c[mt][nt][hi * 2] - M);
            sl += __expf(c[mt][nt][hi * 2 + 1] - M);
        }
        sl += __shfl_xor_sync(0xffffffffu, sl, 1);
        sl += __shfl_xor_sync(0xffffffffu, sl, 2);
        if (tg == 0) sSum[wn][rl] = sl;
    }
    __syncthreads();

    if (tid < 128) {
        float M = fmaxf(sMax[0][tid], sMax[1][tid]);
        g_part[(size_t)(rowbase + tid) * NBLKS + nblk] =
            make_float2(M, sSum[0][tid] + sSum[1][tid]);
    }
}

// ---------------- combine partials -> per-row NLL ----------------------------
__global__ void k_nll2() {
    int r = blockIdx.x, t = threadIdx.x;
    const float2* pp = g_part + (size_t)r * NBLKS;

    float m = -1e30f, s = 0.0f;
    for (int i = t; i < NBLKS; i += 256) {
        float2 p = pp[i];
        if (p.x > m) { s = s * __expf(m - p.x) + p.y; m = p.x; }
        else s += p.y * __expf(p.x - m);
    }
    __shared__ float sm_[256], ss_[256];
    sm_[t] = m; ss_[t] = s; __syncthreads();
    for (int k = 128; k > 0; k >>= 1) {
        if (t < k) {
            float m2 = sm_[t + k], s2 = ss_[t + k];
            float M = fmaxf(sm_[t], m2);
            ss_[t] = ss_[t] * __expf(sm_[t] - M) + s2 * __expf(m2 - M);
            sm_[t] = M;
        }
        __syncthreads();
    }
    if (t == 0) g_rownll[r] = sm_[0] + logf(ss_[0]) - g_tgt[r];
}

__global__ void k_mean(float* __restrict__ out) {
    __shared__ float red[256];
    int t = threadIdx.x;
    float s = 0.0f;
    for (int i = t; i < BT; i += 256) s += g_rownll[i];
    red[t] = s; __syncthreads();
    for (int k = 128; k > 0; k >>= 1) {
        if (t < k) red[t] += red[t + k];
        __syncthreads();
    }
    if (t == 0) out[0] = red[0] / (float)BT;
}

// ---------------- launch -----------------------------------------------------
extern "C" void kernel_launch(void* const* d_in, const int* in_sizes, int n_in,
                              void* d_out, int out_size) {
    const int*   src      = (const int*)  d_in[0];
    const int*   src_len  = (const int*)  d_in[1];
    const int*   trg_in   = (const int*)  d_in[2];
    const int*   trg_out  = (const int*)  d_in[3];
    const float* src_emb  = (const float*)d_in[4];
    const float* trg_emb  = (const float*)d_in[5];
    const float* enc_Wih  = (const float*)d_in[6];
    const float* enc_Whh  = (const float*)d_in[7];
    const float* enc_bih  = (const float*)d_in[8];
    const float* enc_bhh  = (const float*)d_in[9];
    const float* dec_Wi   = (const float*)d_in[10];
    const float* dec_bi   = (const float*)d_in[11];
    const float* dec_Wh   = (const float*)d_in[12];
    const float* dec_bh   = (const float*)d_in[13];
    const float* dec_Wp   = (const float*)d_in[14];
    const float* dec_bp   = (const float*)d_in[15];
    const float* out_W    = (const float*)d_in[16];
    const float* out_b    = (const float*)d_in[17];
    float* out = (float*)d_out;

    // smem: (16+16+32+32)*520 bf16 + (2*32*18 + 128) fp32 = 104,960 B
    const int SMEMB = 96 * 520 * 2 + (2 * 32 * 18 + 128) * 4;
    cudaFuncSetAttribute(k_recur<SLEN, false>,
                         cudaFuncAttributeMaxDynamicSharedMemorySize, SMEMB);
    cudaFuncSetAttribute(k_recur<TLEN, true>,
                         cudaFuncAttributeMaxDynamicSharedMemorySize, SMEMB);

    k_reset_bars<<<1, 1>>>();
    k_zero_h0<<<(BATCH * HID + 255) / 256, 256>>>();

    // gx = emb(src) @ Wih^T + bih   [4096 x 1536]
    k_big_gemm<<<dim3(G3 / 64, SB / 128), 256>>>(src_emb, src, SLEN, SB, EMB,
                                                 enc_Wih, enc_bih, 0, 0);
    // gi = emb(trg) @ Wi^T + bi     [2048 x 1536]
    k_big_gemm<<<dim3(G3 / 64, BT / 128), 256>>>(trg_emb, trg_in, TLEN, BT, EMB,
                                                 dec_Wi, dec_bi, 1, 0);
    // bf16 weights for output projection
    k_conv_w<<<(VOC * HID / 2 + 255) / 256, 256>>>(out_W);

    // encoder: all 128 steps in one persistent kernel
    k_recur<SLEN, false><<<RNBLK, 256, SMEMB>>>(enc_Whh, enc_bhh, src_len);

    // p = ctx @ Wp^T + bp  (ctx = final encoder h in g_h[0]; rows=32 guarded)
    k_big_gemm<<<dim3(G3 / 64, 1), 256>>>(nullptr, nullptr, 0, BATCH, HID,
                                          dec_Wp, dec_bp, 2, 1);

    // decoder: all 64 steps in one persistent kernel (writes g_hb bf16)
    k_recur<TLEN, true><<<RNBLK, 256, SMEMB>>>(dec_Wh, dec_bh, nullptr);

    // output projection + fused partial logsumexp, then combine + mean
    k_out_gemm<<<dim3(NBLKS, BT / 128), 256>>>(out_b, trg_out);
    k_nll2<<<BT, 256>>>();
    k_mean<<<1, 256>>>(out);
}